// round 11
// baseline (speedup 1.0000x reference)
#include <cuda_runtime.h>
#include <cstdint>

// Problem constants
constexpr int B_  = 4;
constexpr int S_  = 2048;
constexpr int D_  = 1024;
constexpr int H_  = 16;
constexpr int DK_ = 64;
constexpr float NEGV = -1000000000.0f;

// Scratch (device globals -- no allocation allowed). Q/K/V/ctx stored
// PRE-ROUNDED to tf32 so consumers skip cvt.
__device__ __align__(16) float g_Q[(size_t)B_*H_*S_*DK_];
__device__ __align__(16) float g_K[(size_t)B_*H_*S_*DK_];
__device__ __align__(16) float g_V[(size_t)B_*H_*S_*DK_];
__device__ __align__(16) float g_ctx[(size_t)B_*S_*D_];
__device__ __align__(16) float g_pre[(size_t)B_*S_*D_];

// ---------------------------------------------------------------------------
// helpers
// ---------------------------------------------------------------------------
__device__ __forceinline__ uint32_t f2tf(float f) {
    uint32_t u;
    asm("cvt.rna.tf32.f32 %0, %1;" : "=r"(u) : "f"(f));
    return u;
}
__device__ __forceinline__ uint32_t tfb(uint32_t bits) {
    return f2tf(__uint_as_float(bits));
}
__device__ __forceinline__ float tff(float f) {
    return __uint_as_float(f2tf(f));
}

__device__ __forceinline__ void mma8(float& c0, float& c1, float& c2, float& c3,
                                     uint32_t a0, uint32_t a1, uint32_t a2, uint32_t a3,
                                     uint32_t b0, uint32_t b1) {
    asm volatile(
        "mma.sync.aligned.m16n8k8.row.col.f32.tf32.tf32.f32 "
        "{%0,%1,%2,%3},{%4,%5,%6,%7},{%8,%9},{%0,%1,%2,%3};\n"
        : "+f"(c0), "+f"(c1), "+f"(c2), "+f"(c3)
        : "r"(a0), "r"(a1), "r"(a2), "r"(a3), "r"(b0), "r"(b1));
}

__device__ __forceinline__ void cpa16(void* dst, const void* src) {
    uint32_t d = (uint32_t)__cvta_generic_to_shared(dst);
    asm volatile("cp.async.cg.shared.global [%0], [%1], 16;" :: "r"(d), "l"(src));
}
__device__ __forceinline__ void cp_commit() {
    asm volatile("cp.async.commit_group;" ::: "memory");
}
__device__ __forceinline__ void cp_wait1() {
    asm volatile("cp.async.wait_group 1;" ::: "memory");
}
__device__ __forceinline__ void cp_wait0() {
    asm volatile("cp.async.wait_group 0;" ::: "memory");
}

// ---------------------------------------------------------------------------
// Kernel 1: fused QKV projection, tf32 mma, cp.async double-buffered.
// grid (8 n-tiles, 64 m-tiles, 3), block 256. CTA tile 128(M) x 128(N), k=32.
// Warp grid 4(M) x 2(N); warp tile 32 x 64 (mi 2 x ni 8).
// Dynamic smem: As[2][128][36] + Bs[2][32][136] = 71,680 B.
// Outputs written tf32-rounded, head-major, Q scaled by 1/8.
// ---------------------------------------------------------------------------
__global__ __launch_bounds__(256) void qkv_kernel(
    const float* __restrict__ x,
    const float* __restrict__ Wq, const float* __restrict__ bq,
    const float* __restrict__ Wk, const float* __restrict__ bk,
    const float* __restrict__ Wv, const float* __restrict__ bv)
{
    const int z = blockIdx.z;
    const float* W    = (z == 0) ? Wq : ((z == 1) ? Wk : Wv);
    const float* bias = (z == 0) ? bq : ((z == 1) ? bk : bv);
    float* outp       = (z == 0) ? g_Q : ((z == 1) ? g_K : g_V);

    const int m0 = blockIdx.y * 128;
    const int n0 = blockIdx.x * 128;

    extern __shared__ uint32_t smq[];
    uint32_t* As = smq;                  // [2][128*36]
    uint32_t* Bs = smq + 2 * 128 * 36;   // [2][32*136]

    const int tid  = threadIdx.x;
    const int wid  = tid >> 5;
    const int lane = tid & 31;
    const int wm   = wid & 3;
    const int wn   = wid >> 2;           // 0..1, 64 cols each
    const int g    = lane >> 2;
    const int t    = lane & 3;

    float c[2][8][4];
    #pragma unroll
    for (int i = 0; i < 2; i++)
        #pragma unroll
        for (int j = 0; j < 8; j++)
            #pragma unroll
            for (int r = 0; r < 4; r++) c[i][j][r] = 0.0f;

    auto stage = [&](int k0, int s) {
        uint32_t* Ad = As + s * (128 * 36);
        uint32_t* Bd = Bs + s * (32 * 136);
        #pragma unroll
        for (int it = 0; it < 4; it++) {
            int idx = tid + it * 256;
            int row = idx >> 3;
            int kc  = (idx & 7) << 2;
            cpa16(Ad + row * 36 + kc, x + (size_t)(m0 + row) * D_ + k0 + kc);
        }
        #pragma unroll
        for (int it = 0; it < 4; it++) {
            int idx = tid + it * 256;
            int k   = idx >> 5;
            int nc  = (idx & 31) << 2;
            cpa16(Bd + k * 136 + nc, W + (size_t)(k0 + k) * D_ + n0 + nc);
        }
        cp_commit();
    };

    stage(0, 0);
    for (int itk = 0; itk < 32; itk++) {
        const int s = itk & 1;
        if (itk < 31) { stage((itk + 1) * 32, s ^ 1); cp_wait1(); }
        else          { cp_wait0(); }
        __syncthreads();

        const uint32_t* Ab = As + s * (128 * 36);
        const uint32_t* Bb = Bs + s * (32 * 136);
        #pragma unroll
        for (int ks = 0; ks < 4; ks++) {
            const int kk = ks << 3;
            uint32_t a[2][4];
            #pragma unroll
            for (int mi = 0; mi < 2; mi++) {
                int mr = wm * 32 + mi * 16 + g;
                a[mi][0] = tfb(Ab[ mr      * 36 + kk + t]);
                a[mi][1] = tfb(Ab[(mr + 8) * 36 + kk + t]);
                a[mi][2] = tfb(Ab[ mr      * 36 + kk + t + 4]);
                a[mi][3] = tfb(Ab[(mr + 8) * 36 + kk + t + 4]);
            }
            uint32_t b[8][2];
            #pragma unroll
            for (int ni = 0; ni < 8; ni++) {
                int nc = wn * 64 + ni * 8 + g;
                b[ni][0] = tfb(Bb[(kk + t    ) * 136 + nc]);
                b[ni][1] = tfb(Bb[(kk + t + 4) * 136 + nc]);
            }
            #pragma unroll
            for (int mi = 0; mi < 2; mi++)
                #pragma unroll
                for (int ni = 0; ni < 8; ni++)
                    mma8(c[mi][ni][0], c[mi][ni][1], c[mi][ni][2], c[mi][ni][3],
                         a[mi][0], a[mi][1], a[mi][2], a[mi][3],
                         b[ni][0], b[ni][1]);
        }
        __syncthreads();
    }

    const float scl = (z == 0) ? 0.125f : 1.0f;   // fold 1/sqrt(64) into Q
    #pragma unroll
    for (int mi = 0; mi < 2; mi++) {
        #pragma unroll
        for (int ni = 0; ni < 8; ni++) {
            int n   = n0 + wn * 64 + ni * 8 + 2 * t;   // global col in D
            int h   = n >> 6;
            int col = n & 63;
            float b0 = bias[n], b1 = bias[n + 1];
            #pragma unroll
            for (int hh = 0; hh < 2; hh++) {
                int m  = m0 + wm * 32 + mi * 16 + g + hh * 8;
                int bb = m >> 11;
                int s2 = m & (S_ - 1);
                float2 o;
                o.x = tff((c[mi][ni][2 * hh + 0] + b0) * scl);
                o.y = tff((c[mi][ni][2 * hh + 1] + b1) * scl);
                *(float2*)(outp + ((size_t)(bb * H_ + h) * S_ + s2) * DK_ + col) = o;
            }
        }
    }
}

// ---------------------------------------------------------------------------
// Kernel 2 (FUSED attention), q-tile 128, 512 threads, warp grid 4(q) x 4(k).
//   Q fragments hoisted to registers; K/V staged raw via cp.async double
//   buffers (pre-rounded in gmem, no cvt needed).
//   pass 1: S = Q@K^T, l = sum exp(S)
//   pass 2: recompute S, p = exp(s)/l, store p to att, scatter p into
//           fragment-order smem (Pf, aliasing Qs), ctx += p@V.
// Dynamic smem: Qs/Pf[128*68] | Ks[2][64*68] | Vs[2][64*72] = 106,496 B.
// ---------------------------------------------------------------------------
__global__ __launch_bounds__(512) void attn_kernel(
    const int* __restrict__ mask, float* __restrict__ att)
{
    extern __shared__ uint32_t dsm[];
    uint32_t (*Qs)[68] = (uint32_t(*)[68])(dsm);       // staged Q (then dead)
    uint32_t* Pf       = dsm;                           // frag-order P (alias)
    uint32_t* KsB      = dsm + 128 * 68;                // [2][64*68]
    uint32_t* VsB      = dsm + 128 * 68 + 2 * 64 * 68;  // [2][64*72]

    __shared__ float red_l[128][4];
    __shared__ float sl[128];

    const int bh = blockIdx.y;
    const int q0 = blockIdx.x * 128;
    const int bb = bh >> 4;

    const float* Qb = g_Q + (size_t)bh * S_ * DK_;
    const float* Kb = g_K + (size_t)bh * S_ * DK_;
    const float* Vb = g_V + (size_t)bh * S_ * DK_;

    const int tid  = threadIdx.x;
    const int wid  = tid >> 5;
    const int lane = tid & 31;
    const int wq   = wid & 3;        // 0..3 (q split, 32 rows each)
    const int wk   = wid >> 2;       // 0..3 (k split, 16 cols each)
    const int g    = lane >> 2;
    const int t    = lane & 3;

    // stage Q tile (128x64, already tf32-rounded) into Qs
    #pragma unroll
    for (int it = 0; it < 4; it++) {
        int idx = tid + it * 512;
        int row = idx >> 4;
        int dc  = (idx & 15) << 2;
        *(uint4*)&Qs[row][dc] = *(const uint4*)(Qb + (size_t)(q0 + row) * DK_ + dc);
    }
    __syncthreads();

    // hoist Q a-fragments into registers (reused by both passes)
    uint32_t qf[2][8][4];
    #pragma unroll
    for (int mi = 0; mi < 2; mi++) {
        int qr = wq * 32 + mi * 16 + g;
        #pragma unroll
        for (int ks = 0; ks < 8; ks++) {
            const int kk = ks << 3;
            qf[mi][ks][0] = Qs[qr    ][kk + t];
            qf[mi][ks][1] = Qs[qr + 8][kk + t];
            qf[mi][ks][2] = Qs[qr    ][kk + t + 4];
            qf[mi][ks][3] = Qs[qr + 8][kk + t + 4];
        }
    }
    __syncthreads();   // Qs dead; Pf may be written in pass 2

    const int* mrow = mask + bb * S_;
    float* attQ = att + (size_t)bh * S_ * S_ + (size_t)q0 * S_;

    auto stageK = [&](int kt, int s) {
        uint32_t* Kd = KsB + s * (64 * 68);
        const float* src = Kb + (size_t)(kt * 64) * DK_;
        #pragma unroll
        for (int it = 0; it < 2; it++) {
            int idx = tid + it * 512;
            int row = idx >> 4;
            int dc  = (idx & 15) << 2;
            cpa16(Kd + row * 68 + dc, src + (size_t)row * DK_ + dc);
        }
    };
    auto stageV = [&](int kt, int s) {
        uint32_t* Vd = VsB + s * (64 * 72);
        const float* src = Vb + (size_t)(kt * 64) * DK_;
        #pragma unroll
        for (int it = 0; it < 2; it++) {
            int idx = tid + it * 512;
            int row = idx >> 4;
            int dc  = (idx & 15) << 2;
            cpa16(Vd + row * 72 + dc, src + (size_t)row * DK_ + dc);
        }
    };

    // ---------------- pass 1: l = sum exp(s) ----------------
    float rl[4] = {0.0f, 0.0f, 0.0f, 0.0f};

    stageK(0, 0); cp_commit();
    for (int kt = 0; kt < 32; kt++) {
        const int s = kt & 1;
        if (kt < 31) { stageK(kt + 1, s ^ 1); cp_commit(); cp_wait1(); }
        else         { cp_wait0(); }
        __syncthreads();

        const uint32_t* Kc = KsB + s * (64 * 68);
        float c[2][2][4];
        #pragma unroll
        for (int mi = 0; mi < 2; mi++)
            #pragma unroll
            for (int ni = 0; ni < 2; ni++)
                #pragma unroll
                for (int r = 0; r < 4; r++) c[mi][ni][r] = 0.0f;

        #pragma unroll
        for (int ks = 0; ks < 8; ks++) {
            const int kk = ks << 3;
            uint32_t b[2][2];
            #pragma unroll
            for (int ni = 0; ni < 2; ni++) {
                int kc = wk * 16 + ni * 8 + g;
                b[ni][0] = Kc[kc * 68 + kk + t];
                b[ni][1] = Kc[kc * 68 + kk + t + 4];
            }
            #pragma unroll
            for (int mi = 0; mi < 2; mi++)
                #pragma unroll
                for (int ni = 0; ni < 2; ni++)
                    mma8(c[mi][ni][0], c[mi][ni][1], c[mi][ni][2], c[mi][ni][3],
                         qf[mi][ks][0], qf[mi][ks][1], qf[mi][ks][2], qf[mi][ks][3],
                         b[ni][0], b[ni][1]);
        }

        #pragma unroll
        for (int ni = 0; ni < 2; ni++) {
            int kg = kt * 64 + wk * 16 + ni * 8 + 2 * t;
            bool mz0 = (mrow[kg] == 0);
            bool mz1 = (mrow[kg + 1] == 0);
            #pragma unroll
            for (int mi = 0; mi < 2; mi++) {
                #pragma unroll
                for (int hh = 0; hh < 2; hh++) {
                    float v0 = mz0 ? NEGV : c[mi][ni][2 * hh + 0];
                    float v1 = mz1 ? NEGV : c[mi][ni][2 * hh + 1];
                    rl[mi * 2 + hh] += __expf(v0) + __expf(v1);
                }
            }
        }
        __syncthreads();
    }

    // reduce l: quad (k-cols within warp), then across wk warps
    #pragma unroll
    for (int i = 0; i < 4; i++) {
        rl[i] += __shfl_xor_sync(0xffffffffu, rl[i], 1);
        rl[i] += __shfl_xor_sync(0xffffffffu, rl[i], 2);
    }
    if (t == 0) {
        #pragma unroll
        for (int mi = 0; mi < 2; mi++)
            #pragma unroll
            for (int hh = 0; hh < 2; hh++) {
                int q = wq * 32 + mi * 16 + g + hh * 8;
                red_l[q][wk] = rl[mi * 2 + hh];
            }
    }
    __syncthreads();
    if (tid < 128) {
        sl[tid] = 1.0f / (red_l[tid][0] + red_l[tid][1] + red_l[tid][2] + red_l[tid][3]);
    }
    __syncthreads();

    // ---------------- pass 2: recompute, normalize, store, AV ----------------
    float co[2][2][4];
    #pragma unroll
    for (int mi = 0; mi < 2; mi++)
        #pragma unroll
        for (int ni = 0; ni < 2; ni++)
            #pragma unroll
            for (int r = 0; r < 4; r++) co[mi][ni][r] = 0.0f;

    stageK(0, 0); stageV(0, 0); cp_commit();
    for (int kt = 0; kt < 32; kt++) {
        const int s = kt & 1;
        if (kt < 31) { stageK(kt + 1, s ^ 1); stageV(kt + 1, s ^ 1); cp_commit(); cp_wait1(); }
        else         { cp_wait0(); }
        __syncthreads();

        const uint32_t* Kc = KsB + s * (64 * 68);
        const uint32_t* Vc = VsB + s * (64 * 72);

        float cs[2][2][4];
        #pragma unroll
        for (int mi = 0; mi < 2; mi++)
            #pragma unroll
            for (int ni = 0; ni < 2; ni++)
                #pragma unroll
                for (int r = 0; r < 4; r++) cs[mi][ni][r] = 0.0f;

        #pragma unroll
        for (int ks = 0; ks < 8; ks++) {
            const int kk = ks << 3;
            uint32_t b[2][2];
            #pragma unroll
            for (int ni = 0; ni < 2; ni++) {
                int kc = wk * 16 + ni * 8 + g;
                b[ni][0] = Kc[kc * 68 + kk + t];
                b[ni][1] = Kc[kc * 68 + kk + t + 4];
            }
            #pragma unroll
            for (int mi = 0; mi < 2; mi++)
                #pragma unroll
                for (int ni = 0; ni < 2; ni++)
                    mma8(cs[mi][ni][0], cs[mi][ni][1], cs[mi][ni][2], cs[mi][ni][3],
                         qf[mi][ks][0], qf[mi][ks][1], qf[mi][ks][2], qf[mi][ks][3],
                         b[ni][0], b[ni][1]);
        }

        // normalize + store att + scatter into fragment-order Pf
        // Pf index: ((mt*8 + kt2)*32 + lane_c)*4 + slot; mt 0..7, kt2 0..7
        #pragma unroll
        for (int ni = 0; ni < 2; ni++) {
            const int kt2 = wk * 2 + ni;
            int kg = kt * 64 + wk * 16 + ni * 8 + 2 * t;
            bool mz0 = (mrow[kg] == 0);
            bool mz1 = (mrow[kg + 1] == 0);
            const int kk0 = 2 * t;
            const int kk1 = 2 * t + 1;
            const int lane0 = g * 4 + (kk0 & 3);
            const int lane1 = g * 4 + (kk1 & 3);
            const int sb0 = (kk0 & 4) >> 1;
            const int sb1 = (kk1 & 4) >> 1;
            #pragma unroll
            for (int mi = 0; mi < 2; mi++) {
                const int mt = wq * 2 + mi;
                uint32_t* base0 = Pf + ((mt * 8 + kt2) * 32 + lane0) * 4 + sb0;
                uint32_t* base1 = Pf + ((mt * 8 + kt2) * 32 + lane1) * 4 + sb1;
                #pragma unroll
                for (int hh = 0; hh < 2; hh++) {
                    int q = wq * 32 + mi * 16 + g + hh * 8;
                    float il = sl[q];
                    float v0 = mz0 ? NEGV : cs[mi][ni][2 * hh + 0];
                    float v1 = mz1 ? NEGV : cs[mi][ni][2 * hh + 1];
                    float p0 = __expf(v0) * il;
                    float p1 = __expf(v1) * il;
                    *(float2*)(attQ + (size_t)q * S_ + kg) = make_float2(p0, p1);
                    base0[hh] = f2tf(p0);
                    base1[hh] = f2tf(p1);
                }
            }
        }
        __syncthreads();

        // AV mma: co += P @ V   (warp owns 32q x 16d, d-split = wk)
        #pragma unroll
        for (int ks = 0; ks < 8; ks++) {
            const int kk = ks << 3;
            uint32_t a[2][4];
            #pragma unroll
            for (int mi = 0; mi < 2; mi++) {
                const int mt = wq * 2 + mi;
                uint4 af = *(const uint4*)(Pf + ((mt * 8 + ks) * 32 + lane) * 4);
                a[mi][0] = af.x; a[mi][1] = af.y; a[mi][2] = af.z; a[mi][3] = af.w;
            }
            uint32_t b[2][2];
            #pragma unroll
            for (int ni = 0; ni < 2; ni++) {
                int dc = wk * 16 + ni * 8 + g;
                b[ni][0] = Vc[(kk + t    ) * 72 + dc];
                b[ni][1] = Vc[(kk + t + 4) * 72 + dc];
            }
            #pragma unroll
            for (int mi = 0; mi < 2; mi++)
                #pragma unroll
                for (int ni = 0; ni < 2; ni++)
                    mma8(co[mi][ni][0], co[mi][ni][1], co[mi][ni][2], co[mi][ni][3],
                         a[mi][0], a[mi][1], a[mi][2], a[mi][3],
                         b[ni][0], b[ni][1]);
        }
        __syncthreads();
    }

    const int h = bh & 15;
    #pragma unroll
    for (int mi = 0; mi < 2; mi++) {
        #pragma unroll
        for (int ni = 0; ni < 2; ni++) {
            int d = wk * 16 + ni * 8 + 2 * t;
            #pragma unroll
            for (int hh = 0; hh < 2; hh++) {
                int q = q0 + wq * 32 + mi * 16 + g + hh * 8;
                float2 o = make_float2(tff(co[mi][ni][2 * hh + 0]),
                                       tff(co[mi][ni][2 * hh + 1]));
                *(float2*)(g_ctx + ((size_t)(bb * S_ + q)) * D_ + h * DK_ + d) = o;
            }
        }
    }
}

// ---------------------------------------------------------------------------
// Kernel 4: out_pre = ctx @ Wo + bo + x  (tf32 mma, cp.async double-buffered,
// residual fused). CTA tile 128x128, k=32. ctx pre-rounded -> no cvt on A.
// ---------------------------------------------------------------------------
__global__ __launch_bounds__(256) void oproj_kernel(
    const float* __restrict__ Wo, const float* __restrict__ bo,
    const float* __restrict__ x)
{
    const int m0 = blockIdx.y * 128;
    const int n0 = blockIdx.x * 128;

    extern __shared__ uint32_t smo[];
    uint32_t* As = smo;
    uint32_t* Bs = smo + 2 * 128 * 36;

    const int tid  = threadIdx.x;
    const int wid  = tid >> 5;
    const int lane = tid & 31;
    const int wm   = wid & 3;
    const int wn   = wid >> 2;
    const int g    = lane >> 2;
    const int t    = lane & 3;

    float c[2][8][4];
    #pragma unroll
    for (int i = 0; i < 2; i++)
        #pragma unroll
        for (int j = 0; j < 8; j++)
            #pragma unroll
            for (int r = 0; r < 4; r++) c[i][j][r] = 0.0f;

    auto stage = [&](int k0, int s) {
        uint32_t* Ad = As + s * (128 * 36);
        uint32_t* Bd = Bs + s * (32 * 136);
        #pragma unroll
        for (int it = 0; it < 4; it++) {
            int idx = tid + it * 256;
            int row = idx >> 3;
            int kc  = (idx & 7) << 2;
            cpa16(Ad + row * 36 + kc, g_ctx + (size_t)(m0 + row) * D_ + k0 + kc);
        }
        #pragma unroll
        for (int it = 0; it < 4; it++) {
            int idx = tid + it * 256;
            int k   = idx >> 5;
            int nc  = (idx & 31) << 2;
            cpa16(Bd + k * 136 + nc, Wo + (size_t)(k0 + k) * D_ + n0 + nc);
        }
        cp_commit();
    };

    stage(0, 0);
    for (int itk = 0; itk < 32; itk++) {
        const int s = itk & 1;
        if (itk < 31) { stage((itk + 1) * 32, s ^ 1); cp_wait1(); }
        else          { cp_wait0(); }
        __syncthreads();

        const uint32_t* Ab = As + s * (128 * 36);
        const uint32_t* Bb = Bs + s * (32 * 136);
        #pragma unroll
        for (int ks = 0; ks < 4; ks++) {
            const int kk = ks << 3;
            uint32_t a[2][4];
            #pragma unroll
            for (int mi = 0; mi < 2; mi++) {
                int mr = wm * 32 + mi * 16 + g;
                a[mi][0] = Ab[ mr      * 36 + kk + t];
                a[mi][1] = Ab[(mr + 8) * 36 + kk + t];
                a[mi][2] = Ab[ mr      * 36 + kk + t + 4];
                a[mi][3] = Ab[(mr + 8) * 36 + kk + t + 4];
            }
            uint32_t b[8][2];
            #pragma unroll
            for (int ni = 0; ni < 8; ni++) {
                int nc = wn * 64 + ni * 8 + g;
                b[ni][0] = tfb(Bb[(kk + t    ) * 136 + nc]);
                b[ni][1] = tfb(Bb[(kk + t + 4) * 136 + nc]);
            }
            #pragma unroll
            for (int mi = 0; mi < 2; mi++)
                #pragma unroll
                for (int ni = 0; ni < 8; ni++)
                    mma8(c[mi][ni][0], c[mi][ni][1], c[mi][ni][2], c[mi][ni][3],
                         a[mi][0], a[mi][1], a[mi][2], a[mi][3],
                         b[ni][0], b[ni][1]);
        }
        __syncthreads();
    }

    #pragma unroll
    for (int mi = 0; mi < 2; mi++) {
        #pragma unroll
        for (int ni = 0; ni < 8; ni++) {
            int n = n0 + wn * 64 + ni * 8 + 2 * t;
            float b0 = bo[n], b1 = bo[n + 1];
            #pragma unroll
            for (int hh = 0; hh < 2; hh++) {
                int m = m0 + wm * 32 + mi * 16 + g + hh * 8;
                float2 xr = *(const float2*)(x + (size_t)m * D_ + n);
                float2 o;
                o.x = c[mi][ni][2 * hh + 0] + b0 + xr.x;
                o.y = c[mi][ni][2 * hh + 1] + b1 + xr.y;
                *(float2*)(g_pre + (size_t)m * D_ + n) = o;
            }
        }
    }
}

// ---------------------------------------------------------------------------
// Kernel 5: rowwise LayerNorm.  grid 8192, block 256.
// ---------------------------------------------------------------------------
__global__ __launch_bounds__(256) void ln_kernel(
    const float* __restrict__ gamma, const float* __restrict__ beta,
    float* __restrict__ out)
{
    const int row = blockIdx.x;
    const float* pr = g_pre + (size_t)row * D_;

    float s = 0.0f, ss = 0.0f;
    for (int i = threadIdx.x; i < D_; i += 256) {
        float t = pr[i];
        s += t; ss += t * t;
    }
    #pragma unroll
    for (int o = 16; o > 0; o >>= 1) {
        s  += __shfl_down_sync(0xffffffffu, s, o);
        ss += __shfl_down_sync(0xffffffffu, ss, o);
    }
    __shared__ float rs[8], rss[8];
    __shared__ float s_mu, s_inv;
    int w = threadIdx.x >> 5, lane = threadIdx.x & 31;
    if (lane == 0) { rs[w] = s; rss[w] = ss; }
    __syncthreads();
    if (threadIdx.x == 0) {
        float S = 0.0f, SS = 0.0f;
        #pragma unroll
        for (int q = 0; q < 8; q++) { S += rs[q]; SS += rss[q]; }
        float mu  = S * (1.0f / (float)D_);
        float var = SS * (1.0f / (float)D_) - mu * mu;
        var = fmaxf(var, 0.0f);
        s_mu  = mu;
        s_inv = rsqrtf(var + 1e-5f);
    }
    __syncthreads();
    float mu = s_mu, inv = s_inv;
    for (int i = threadIdx.x; i < D_; i += 256) {
        out[(size_t)row * D_ + i] = (pr[i] - mu) * inv * gamma[i] + beta[i];
    }
}

// ---------------------------------------------------------------------------
extern "C" void kernel_launch(void* const* d_in, const int* in_sizes, int n_in,
                              void* d_out, int out_size)
{
    const float* x     = (const float*)d_in[0];
    const int*   mask  = (const int*)  d_in[1];
    const float* Wq    = (const float*)d_in[2];
    const float* bq    = (const float*)d_in[3];
    const float* Wk    = (const float*)d_in[4];
    const float* bk    = (const float*)d_in[5];
    const float* Wv    = (const float*)d_in[6];
    const float* bv    = (const float*)d_in[7];
    const float* Wo    = (const float*)d_in[8];
    const float* bo    = (const float*)d_in[9];
    const float* gamma = (const float*)d_in[10];
    const float* beta  = (const float*)d_in[11];

    float* out = (float*)d_out;
    float* att = out + (size_t)B_ * S_ * D_;

    constexpr int GEMM_SMEM = (2 * 128 * 36 + 2 * 32 * 136) * 4;          // 71,680 B
    constexpr int ATTN_SMEM = (128 * 68 + 2 * 64 * 68 + 2 * 64 * 72) * 4; // 106,496 B

    cudaFuncSetAttribute(qkv_kernel,
                         cudaFuncAttributeMaxDynamicSharedMemorySize, GEMM_SMEM);
    cudaFuncSetAttribute(oproj_kernel,
                         cudaFuncAttributeMaxDynamicSharedMemorySize, GEMM_SMEM);
    cudaFuncSetAttribute(attn_kernel,
                         cudaFuncAttributeMaxDynamicSharedMemorySize, ATTN_SMEM);

    qkv_kernel<<<dim3(8, 64, 3), 256, GEMM_SMEM>>>(x, Wq, bq, Wk, bk, Wv, bv);
    attn_kernel<<<dim3(16, 64), 512, ATTN_SMEM>>>(mask, att);
    oproj_kernel<<<dim3(8, 64), 256, GEMM_SMEM>>>(Wo, bo, x);
    ln_kernel<<<8192, 256>>>(gamma, beta, out);
}

// round 12
// speedup vs baseline: 1.0389x; 1.0389x over previous
#include <cuda_runtime.h>
#include <cstdint>

// Problem constants
constexpr int B_  = 4;
constexpr int S_  = 2048;
constexpr int D_  = 1024;
constexpr int H_  = 16;
constexpr int DK_ = 64;
constexpr float NEGV = -1000000000.0f;

// Scratch (device globals -- no allocation allowed). Q/K/V/ctx stored
// PRE-ROUNDED to tf32 so consumers skip cvt.
__device__ __align__(16) float g_Q[(size_t)B_*H_*S_*DK_];
__device__ __align__(16) float g_K[(size_t)B_*H_*S_*DK_];
__device__ __align__(16) float g_V[(size_t)B_*H_*S_*DK_];
__device__ __align__(16) float g_ctx[(size_t)B_*S_*D_];
__device__ __align__(16) float g_pre[(size_t)B_*S_*D_];

// ---------------------------------------------------------------------------
// helpers
// ---------------------------------------------------------------------------
__device__ __forceinline__ uint32_t f2tf(float f) {
    uint32_t u;
    asm("cvt.rna.tf32.f32 %0, %1;" : "=r"(u) : "f"(f));
    return u;
}
__device__ __forceinline__ uint32_t tfb(uint32_t bits) {
    return f2tf(__uint_as_float(bits));
}
__device__ __forceinline__ float tff(float f) {
    return __uint_as_float(f2tf(f));
}

__device__ __forceinline__ void mma8(float& c0, float& c1, float& c2, float& c3,
                                     uint32_t a0, uint32_t a1, uint32_t a2, uint32_t a3,
                                     uint32_t b0, uint32_t b1) {
    asm volatile(
        "mma.sync.aligned.m16n8k8.row.col.f32.tf32.tf32.f32 "
        "{%0,%1,%2,%3},{%4,%5,%6,%7},{%8,%9},{%0,%1,%2,%3};\n"
        : "+f"(c0), "+f"(c1), "+f"(c2), "+f"(c3)
        : "r"(a0), "r"(a1), "r"(a2), "r"(a3), "r"(b0), "r"(b1));
}

__device__ __forceinline__ void cpa16(void* dst, const void* src) {
    uint32_t d = (uint32_t)__cvta_generic_to_shared(dst);
    asm volatile("cp.async.cg.shared.global [%0], [%1], 16;" :: "r"(d), "l"(src));
}
__device__ __forceinline__ void cp_commit() {
    asm volatile("cp.async.commit_group;" ::: "memory");
}
__device__ __forceinline__ void cp_wait1() {
    asm volatile("cp.async.wait_group 1;" ::: "memory");
}
__device__ __forceinline__ void cp_wait0() {
    asm volatile("cp.async.wait_group 0;" ::: "memory");
}

// ---------------------------------------------------------------------------
// Kernel 1: fused QKV projection, tf32 mma, cp.async double-buffered.
// grid (16 n-tiles, 64 m-tiles, 3), block 256. CTA tile 128(M) x 64(N), k=32.
// Dynamic smem: As[2][128][36] + Bs[2][32][72] = 55,296 B (raw fp32 bits).
// Outputs written tf32-rounded, head-major, Q scaled by 1/8.
// ---------------------------------------------------------------------------
__global__ __launch_bounds__(256) void qkv_kernel(
    const float* __restrict__ x,
    const float* __restrict__ Wq, const float* __restrict__ bq,
    const float* __restrict__ Wk, const float* __restrict__ bk,
    const float* __restrict__ Wv, const float* __restrict__ bv)
{
    const int z = blockIdx.z;
    const float* W    = (z == 0) ? Wq : ((z == 1) ? Wk : Wv);
    const float* bias = (z == 0) ? bq : ((z == 1) ? bk : bv);
    float* outp       = (z == 0) ? g_Q : ((z == 1) ? g_K : g_V);

    const int m0 = blockIdx.y * 128;
    const int n0 = blockIdx.x * 64;
    const int h  = blockIdx.x;

    extern __shared__ uint32_t smq[];
    uint32_t* As = smq;                 // [2][128*36]
    uint32_t* Bs = smq + 2 * 128 * 36;  // [2][32*72]

    const int tid  = threadIdx.x;
    const int wid  = tid >> 5;
    const int lane = tid & 31;
    const int wm   = wid & 3;
    const int wn   = wid >> 2;
    const int g    = lane >> 2;
    const int t    = lane & 3;

    float c[2][4][4];
    #pragma unroll
    for (int i = 0; i < 2; i++)
        #pragma unroll
        for (int j = 0; j < 4; j++)
            #pragma unroll
            for (int r = 0; r < 4; r++) c[i][j][r] = 0.0f;

    auto stage = [&](int k0, int s) {
        uint32_t* Ad = As + s * (128 * 36);
        uint32_t* Bd = Bs + s * (32 * 72);
        #pragma unroll
        for (int it = 0; it < 4; it++) {
            int idx = tid + it * 256;
            int row = idx >> 3;
            int kc  = (idx & 7) << 2;
            cpa16(Ad + row * 36 + kc, x + (size_t)(m0 + row) * D_ + k0 + kc);
        }
        #pragma unroll
        for (int it = 0; it < 2; it++) {
            int idx = tid + it * 256;
            int k   = idx >> 4;
            int nc  = (idx & 15) << 2;
            cpa16(Bd + k * 72 + nc, W + (size_t)(k0 + k) * D_ + n0 + nc);
        }
        cp_commit();
    };

    stage(0, 0);
    for (int itk = 0; itk < 32; itk++) {
        const int s = itk & 1;
        if (itk < 31) { stage((itk + 1) * 32, s ^ 1); cp_wait1(); }
        else          { cp_wait0(); }
        __syncthreads();

        const uint32_t* Ab = As + s * (128 * 36);
        const uint32_t* Bb = Bs + s * (32 * 72);
        #pragma unroll
        for (int ks = 0; ks < 4; ks++) {
            const int kk = ks << 3;
            uint32_t a[2][4];
            #pragma unroll
            for (int mi = 0; mi < 2; mi++) {
                int mr = wm * 32 + mi * 16 + g;
                a[mi][0] = tfb(Ab[ mr      * 36 + kk + t]);
                a[mi][1] = tfb(Ab[(mr + 8) * 36 + kk + t]);
                a[mi][2] = tfb(Ab[ mr      * 36 + kk + t + 4]);
                a[mi][3] = tfb(Ab[(mr + 8) * 36 + kk + t + 4]);
            }
            uint32_t b[4][2];
            #pragma unroll
            for (int ni = 0; ni < 4; ni++) {
                int nc = wn * 32 + ni * 8 + g;
                b[ni][0] = tfb(Bb[(kk + t    ) * 72 + nc]);
                b[ni][1] = tfb(Bb[(kk + t + 4) * 72 + nc]);
            }
            #pragma unroll
            for (int mi = 0; mi < 2; mi++)
                #pragma unroll
                for (int ni = 0; ni < 4; ni++)
                    mma8(c[mi][ni][0], c[mi][ni][1], c[mi][ni][2], c[mi][ni][3],
                         a[mi][0], a[mi][1], a[mi][2], a[mi][3],
                         b[ni][0], b[ni][1]);
        }
        __syncthreads();
    }

    const float scl = (z == 0) ? 0.125f : 1.0f;   // fold 1/sqrt(64) into Q
    #pragma unroll
    for (int mi = 0; mi < 2; mi++) {
        #pragma unroll
        for (int ni = 0; ni < 4; ni++) {
            int n  = wn * 32 + ni * 8 + 2 * t;
            float b0 = bias[n0 + n], b1 = bias[n0 + n + 1];
            #pragma unroll
            for (int hh = 0; hh < 2; hh++) {
                int m  = m0 + wm * 32 + mi * 16 + g + hh * 8;
                int bb = m >> 11;
                int s2 = m & (S_ - 1);
                float2 o;
                o.x = tff((c[mi][ni][2 * hh + 0] + b0) * scl);
                o.y = tff((c[mi][ni][2 * hh + 1] + b1) * scl);
                *(float2*)(outp + ((size_t)(bb * H_ + h) * S_ + s2) * DK_ + n) = o;
            }
        }
    }
}

// ---------------------------------------------------------------------------
// Kernel 2 (FUSED attention, single-QK): q-tile 64, 256 threads,
// warp grid 2(q) x 4(k).
//   pass 1: S = Q@K^T (Q frags in regs), e = exp(masked s) -> STORE e to att
//           (unnormalized; masked cols give exp(-1e9) = 0), accumulate l.
//   pass 2: cp.async e back from att (L2-resident strip), p = e/l,
//           rewrite att with p (coalesced STG.128), stage tf32(p) in smem,
//           ctx += p@V.  NO second QK^T, no second exp.
// Dynamic smem: Es0[64*68] (= pass1 Qs) | Ks[2][64*68] (pass2: Es1 in first
// half) | Vs[2][64*72]  = 89,088 B.
// ---------------------------------------------------------------------------
__global__ __launch_bounds__(256, 2) void attn_kernel(
    const int* __restrict__ mask, float* __restrict__ att)
{
    extern __shared__ uint32_t dsm[];
    uint32_t (*Qs)[68] = (uint32_t(*)[68])(dsm);       // staged Q (then Es buf0)
    uint32_t* EsB[2]   = { dsm, dsm + 64 * 68 };        // pass2 e/p tiles
    uint32_t* KsB      = dsm + 64 * 68;                 // pass1 [2][64*68]
    uint32_t* VsB      = dsm + 3 * 64 * 68;             // [2][64*72]

    __shared__ float red_l[64][4];
    __shared__ float sl[64];

    const int bh = blockIdx.y;
    const int q0 = blockIdx.x * 64;
    const int bb = bh >> 4;

    const float* Qb = g_Q + (size_t)bh * S_ * DK_;
    const float* Kb = g_K + (size_t)bh * S_ * DK_;
    const float* Vb = g_V + (size_t)bh * S_ * DK_;

    const int tid  = threadIdx.x;
    const int wid  = tid >> 5;
    const int lane = tid & 31;
    const int wq   = wid & 1;
    const int wk   = wid >> 1;
    const int g    = lane >> 2;
    const int t    = lane & 3;

    // stage Q tile (64x64, already tf32-rounded) into Qs
    #pragma unroll
    for (int it = 0; it < 4; it++) {
        int idx = tid + it * 256;
        int row = idx >> 4;
        int dc  = (idx & 15) << 2;
        *(uint4*)&Qs[row][dc] = *(const uint4*)(Qb + (size_t)(q0 + row) * DK_ + dc);
    }
    __syncthreads();

    // hoist Q a-fragments into registers (pass 1 only)
    uint32_t qf[2][8][4];
    #pragma unroll
    for (int mi = 0; mi < 2; mi++) {
        int qr = wq * 32 + mi * 16 + g;
        #pragma unroll
        for (int ks = 0; ks < 8; ks++) {
            const int kk = ks << 3;
            qf[mi][ks][0] = Qs[qr    ][kk + t];
            qf[mi][ks][1] = Qs[qr + 8][kk + t];
            qf[mi][ks][2] = Qs[qr    ][kk + t + 4];
            qf[mi][ks][3] = Qs[qr + 8][kk + t + 4];
        }
    }
    __syncthreads();   // Qs dead; region reused as Es buf0 in pass 2

    const int* mrow = mask + bb * S_;
    float* attQ = att + (size_t)bh * S_ * S_ + (size_t)q0 * S_;

    auto stageK = [&](int kt, int s) {
        uint32_t* Kd = KsB + s * (64 * 68);
        const float* src = Kb + (size_t)(kt * 64) * DK_;
        #pragma unroll
        for (int it = 0; it < 4; it++) {
            int idx = tid + it * 256;
            int row = idx >> 4;
            int dc  = (idx & 15) << 2;
            cpa16(Kd + row * 68 + dc, src + (size_t)row * DK_ + dc);
        }
    };
    auto stageV = [&](int kt, int s) {
        uint32_t* Vd = VsB + s * (64 * 72);
        const float* src = Vb + (size_t)(kt * 64) * DK_;
        #pragma unroll
        for (int it = 0; it < 4; it++) {
            int idx = tid + it * 256;
            int row = idx >> 4;
            int dc  = (idx & 15) << 2;
            cpa16(Vd + row * 72 + dc, src + (size_t)row * DK_ + dc);
        }
    };
    auto stageE = [&](int kt, int s) {
        uint32_t* Ed = EsB[s];
        const float* src = attQ + kt * 64;
        #pragma unroll
        for (int it = 0; it < 4; it++) {
            int idx = tid + it * 256;
            int row = idx >> 4;
            int kc  = (idx & 15) << 2;
            cpa16(Ed + row * 68 + kc, src + (size_t)row * S_ + kc);
        }
    };

    // ---------------- pass 1: e = exp(s) -> att, l = sum e ----------------
    float rl[4] = {0.0f, 0.0f, 0.0f, 0.0f};

    stageK(0, 0); cp_commit();
    for (int kt = 0; kt < 32; kt++) {
        const int s = kt & 1;
        if (kt < 31) { stageK(kt + 1, s ^ 1); cp_commit(); cp_wait1(); }
        else         { cp_wait0(); }
        __syncthreads();

        const uint32_t* Kc = KsB + s * (64 * 68);
        float c[2][2][4];
        #pragma unroll
        for (int mi = 0; mi < 2; mi++)
            #pragma unroll
            for (int ni = 0; ni < 2; ni++)
                #pragma unroll
                for (int r = 0; r < 4; r++) c[mi][ni][r] = 0.0f;

        #pragma unroll
        for (int ks = 0; ks < 8; ks++) {
            const int kk = ks << 3;
            uint32_t b[2][2];
            #pragma unroll
            for (int ni = 0; ni < 2; ni++) {
                int kc = wk * 16 + ni * 8 + g;
                b[ni][0] = Kc[kc * 68 + kk + t];
                b[ni][1] = Kc[kc * 68 + kk + t + 4];
            }
            #pragma unroll
            for (int mi = 0; mi < 2; mi++)
                #pragma unroll
                for (int ni = 0; ni < 2; ni++)
                    mma8(c[mi][ni][0], c[mi][ni][1], c[mi][ni][2], c[mi][ni][3],
                         qf[mi][ks][0], qf[mi][ks][1], qf[mi][ks][2], qf[mi][ks][3],
                         b[ni][0], b[ni][1]);
        }

        #pragma unroll
        for (int ni = 0; ni < 2; ni++) {
            int kg = kt * 64 + wk * 16 + ni * 8 + 2 * t;
            bool mz0 = (mrow[kg] == 0);
            bool mz1 = (mrow[kg + 1] == 0);
            #pragma unroll
            for (int mi = 0; mi < 2; mi++) {
                #pragma unroll
                for (int hh = 0; hh < 2; hh++) {
                    int q = wq * 32 + mi * 16 + g + hh * 8;
                    float v0 = mz0 ? NEGV : c[mi][ni][2 * hh + 0];
                    float v1 = mz1 ? NEGV : c[mi][ni][2 * hh + 1];
                    float e0 = __expf(v0);
                    float e1 = __expf(v1);
                    rl[mi * 2 + hh] += e0 + e1;
                    *(float2*)(attQ + (size_t)q * S_ + kg) = make_float2(e0, e1);
                }
            }
        }
        __syncthreads();
    }

    // reduce l: quad (k-cols within warp), then across wk warps
    #pragma unroll
    for (int i = 0; i < 4; i++) {
        rl[i] += __shfl_xor_sync(0xffffffffu, rl[i], 1);
        rl[i] += __shfl_xor_sync(0xffffffffu, rl[i], 2);
    }
    if (t == 0) {
        #pragma unroll
        for (int mi = 0; mi < 2; mi++)
            #pragma unroll
            for (int hh = 0; hh < 2; hh++) {
                int q = wq * 32 + mi * 16 + g + hh * 8;
                red_l[q][wk] = rl[mi * 2 + hh];
            }
    }
    __syncthreads();
    if (tid < 64) {
        sl[tid] = 1.0f / (red_l[tid][0] + red_l[tid][1] + red_l[tid][2] + red_l[tid][3]);
    }
    __syncthreads();   // all e-stores + sl visible before pass 2 reads

    // ---------------- pass 2: reload e, p = e/l, rewrite att, AV ----------------
    float co[2][2][4];
    #pragma unroll
    for (int mi = 0; mi < 2; mi++)
        #pragma unroll
        for (int ni = 0; ni < 2; ni++)
            #pragma unroll
            for (int r = 0; r < 4; r++) co[mi][ni][r] = 0.0f;

    stageE(0, 0); stageV(0, 0); cp_commit();
    for (int kt = 0; kt < 32; kt++) {
        const int s = kt & 1;
        if (kt < 31) { stageE(kt + 1, s ^ 1); stageV(kt + 1, s ^ 1); cp_commit(); cp_wait1(); }
        else         { cp_wait0(); }
        __syncthreads();

        uint32_t* Ec = EsB[s];
        const uint32_t* Vc = VsB + s * (64 * 72);

        // normalize sweep: p = e * (1/l); STG.128 to att; overwrite Ec with tf32(p)
        #pragma unroll
        for (int it = 0; it < 4; it++) {
            int idx = tid + it * 256;
            int row = idx >> 4;
            int kc  = (idx & 15) << 2;
            float4 e = *(float4*)&Ec[row * 68 + kc];
            float il = sl[row];
            float4 p;
            p.x = e.x * il; p.y = e.y * il; p.z = e.z * il; p.w = e.w * il;
            *(float4*)(attQ + (size_t)row * S_ + kt * 64 + kc) = p;
            uint4 pt = make_uint4(f2tf(p.x), f2tf(p.y), f2tf(p.z), f2tf(p.w));
            *(uint4*)&Ec[row * 68 + kc] = pt;
        }
        __syncthreads();

        // AV mma: co += P @ V   (A-frags straight from Ec [row][k], stride 68)
        #pragma unroll
        for (int ks = 0; ks < 8; ks++) {
            const int kk = ks << 3;
            uint32_t a[2][4];
            #pragma unroll
            for (int mi = 0; mi < 2; mi++) {
                int qr = wq * 32 + mi * 16 + g;
                a[mi][0] = Ec[ qr      * 68 + kk + t];
                a[mi][1] = Ec[(qr + 8) * 68 + kk + t];
                a[mi][2] = Ec[ qr      * 68 + kk + t + 4];
                a[mi][3] = Ec[(qr + 8) * 68 + kk + t + 4];
            }
            uint32_t b[2][2];
            #pragma unroll
            for (int ni = 0; ni < 2; ni++) {
                int dc = wk * 16 + ni * 8 + g;
                b[ni][0] = Vc[(kk + t    ) * 72 + dc];
                b[ni][1] = Vc[(kk + t + 4) * 72 + dc];
            }
            #pragma unroll
            for (int mi = 0; mi < 2; mi++)
                #pragma unroll
                for (int ni = 0; ni < 2; ni++)
                    mma8(co[mi][ni][0], co[mi][ni][1], co[mi][ni][2], co[mi][ni][3],
                         a[mi][0], a[mi][1], a[mi][2], a[mi][3],
                         b[ni][0], b[ni][1]);
        }
        __syncthreads();
    }

    const int h = bh & 15;
    #pragma unroll
    for (int mi = 0; mi < 2; mi++) {
        #pragma unroll
        for (int ni = 0; ni < 2; ni++) {
            int d = wk * 16 + ni * 8 + 2 * t;
            #pragma unroll
            for (int hh = 0; hh < 2; hh++) {
                int q = q0 + wq * 32 + mi * 16 + g + hh * 8;
                float2 o = make_float2(tff(co[mi][ni][2 * hh + 0]),
                                       tff(co[mi][ni][2 * hh + 1]));
                *(float2*)(g_ctx + ((size_t)(bb * S_ + q)) * D_ + h * DK_ + d) = o;
            }
        }
    }
}

// ---------------------------------------------------------------------------
// Kernel 4: out_pre = ctx @ Wo + bo + x  (tf32 mma, cp.async double-buffered,
// residual fused). ctx is pre-rounded -> no cvt on A; Wo gets post-LDS cvt.
// ---------------------------------------------------------------------------
__global__ __launch_bounds__(256) void oproj_kernel(
    const float* __restrict__ Wo, const float* __restrict__ bo,
    const float* __restrict__ x)
{
    const int m0 = blockIdx.y * 128;
    const int n0 = blockIdx.x * 64;

    extern __shared__ uint32_t smo[];
    uint32_t* As = smo;
    uint32_t* Bs = smo + 2 * 128 * 36;

    const int tid  = threadIdx.x;
    const int wid  = tid >> 5;
    const int lane = tid & 31;
    const int wm   = wid & 3;
    const int wn   = wid >> 2;
    const int g    = lane >> 2;
    const int t    = lane & 3;

    float c[2][4][4];
    #pragma unroll
    for (int i = 0; i < 2; i++)
        #pragma unroll
        for (int j = 0; j < 4; j++)
            #pragma unroll
            for (int r = 0; r < 4; r++) c[i][j][r] = 0.0f;

    auto stage = [&](int k0, int s) {
        uint32_t* Ad = As + s * (128 * 36);
        uint32_t* Bd = Bs + s * (32 * 72);
        #pragma unroll
        for (int it = 0; it < 4; it++) {
            int idx = tid + it * 256;
            int row = idx >> 3;
            int kc  = (idx & 7) << 2;
            cpa16(Ad + row * 36 + kc, g_ctx + (size_t)(m0 + row) * D_ + k0 + kc);
        }
        #pragma unroll
        for (int it = 0; it < 2; it++) {
            int idx = tid + it * 256;
            int k   = idx >> 4;
            int nc  = (idx & 15) << 2;
            cpa16(Bd + k * 72 + nc, Wo + (size_t)(k0 + k) * D_ + n0 + nc);
        }
        cp_commit();
    };

    stage(0, 0);
    for (int itk = 0; itk < 32; itk++) {
        const int s = itk & 1;
        if (itk < 31) { stage((itk + 1) * 32, s ^ 1); cp_wait1(); }
        else          { cp_wait0(); }
        __syncthreads();

        const uint32_t* Ab = As + s * (128 * 36);
        const uint32_t* Bb = Bs + s * (32 * 72);
        #pragma unroll
        for (int ks = 0; ks < 4; ks++) {
            const int kk = ks << 3;
            uint32_t a[2][4];
            #pragma unroll
            for (int mi = 0; mi < 2; mi++) {
                int mr = wm * 32 + mi * 16 + g;
                a[mi][0] = Ab[ mr      * 36 + kk + t];
                a[mi][1] = Ab[(mr + 8) * 36 + kk + t];
                a[mi][2] = Ab[ mr      * 36 + kk + t + 4];
                a[mi][3] = Ab[(mr + 8) * 36 + kk + t + 4];
            }
            uint32_t b[4][2];
            #pragma unroll
            for (int ni = 0; ni < 4; ni++) {
                int nc = wn * 32 + ni * 8 + g;
                b[ni][0] = tfb(Bb[(kk + t    ) * 72 + nc]);
                b[ni][1] = tfb(Bb[(kk + t + 4) * 72 + nc]);
            }
            #pragma unroll
            for (int mi = 0; mi < 2; mi++)
                #pragma unroll
                for (int ni = 0; ni < 4; ni++)
                    mma8(c[mi][ni][0], c[mi][ni][1], c[mi][ni][2], c[mi][ni][3],
                         a[mi][0], a[mi][1], a[mi][2], a[mi][3],
                         b[ni][0], b[ni][1]);
        }
        __syncthreads();
    }

    #pragma unroll
    for (int mi = 0; mi < 2; mi++) {
        #pragma unroll
        for (int ni = 0; ni < 4; ni++) {
            int n = n0 + wn * 32 + ni * 8 + 2 * t;
            float b0 = bo[n], b1 = bo[n + 1];
            #pragma unroll
            for (int hh = 0; hh < 2; hh++) {
                int m = m0 + wm * 32 + mi * 16 + g + hh * 8;
                float2 xr = *(const float2*)(x + (size_t)m * D_ + n);
                float2 o;
                o.x = c[mi][ni][2 * hh + 0] + b0 + xr.x;
                o.y = c[mi][ni][2 * hh + 1] + b1 + xr.y;
                *(float2*)(g_pre + (size_t)m * D_ + n) = o;
            }
        }
    }
}

// ---------------------------------------------------------------------------
// Kernel 5: rowwise LayerNorm.  grid 8192, block 256.
// ---------------------------------------------------------------------------
__global__ __launch_bounds__(256) void ln_kernel(
    const float* __restrict__ gamma, const float* __restrict__ beta,
    float* __restrict__ out)
{
    const int row = blockIdx.x;
    const float* pr = g_pre + (size_t)row * D_;

    float s = 0.0f, ss = 0.0f;
    for (int i = threadIdx.x; i < D_; i += 256) {
        float t = pr[i];
        s += t; ss += t * t;
    }
    #pragma unroll
    for (int o = 16; o > 0; o >>= 1) {
        s  += __shfl_down_sync(0xffffffffu, s, o);
        ss += __shfl_down_sync(0xffffffffu, ss, o);
    }
    __shared__ float rs[8], rss[8];
    __shared__ float s_mu, s_inv;
    int w = threadIdx.x >> 5, lane = threadIdx.x & 31;
    if (lane == 0) { rs[w] = s; rss[w] = ss; }
    __syncthreads();
    if (threadIdx.x == 0) {
        float S = 0.0f, SS = 0.0f;
        #pragma unroll
        for (int q = 0; q < 8; q++) { S += rs[q]; SS += rss[q]; }
        float mu  = S * (1.0f / (float)D_);
        float var = SS * (1.0f / (float)D_) - mu * mu;
        var = fmaxf(var, 0.0f);
        s_mu  = mu;
        s_inv = rsqrtf(var + 1e-5f);
    }
    __syncthreads();
    float mu = s_mu, inv = s_inv;
    for (int i = threadIdx.x; i < D_; i += 256) {
        out[(size_t)row * D_ + i] = (pr[i] - mu) * inv * gamma[i] + beta[i];
    }
}

// ---------------------------------------------------------------------------
extern "C" void kernel_launch(void* const* d_in, const int* in_sizes, int n_in,
                              void* d_out, int out_size)
{
    const float* x     = (const float*)d_in[0];
    const int*   mask  = (const int*)  d_in[1];
    const float* Wq    = (const float*)d_in[2];
    const float* bq    = (const float*)d_in[3];
    const float* Wk    = (const float*)d_in[4];
    const float* bk    = (const float*)d_in[5];
    const float* Wv    = (const float*)d_in[6];
    const float* bv    = (const float*)d_in[7];
    const float* Wo    = (const float*)d_in[8];
    const float* bo    = (const float*)d_in[9];
    const float* gamma = (const float*)d_in[10];
    const float* beta  = (const float*)d_in[11];

    float* out = (float*)d_out;
    float* att = out + (size_t)B_ * S_ * D_;

    constexpr int GEMM_SMEM = (2 * 128 * 36 + 2 * 32 * 72) * 4;          // 55,296 B
    constexpr int ATTN_SMEM = (64 * 68 + 2 * 64 * 68 + 2 * 64 * 72) * 4; // 89,088 B

    cudaFuncSetAttribute(qkv_kernel,
                         cudaFuncAttributeMaxDynamicSharedMemorySize, GEMM_SMEM);
    cudaFuncSetAttribute(oproj_kernel,
                         cudaFuncAttributeMaxDynamicSharedMemorySize, GEMM_SMEM);
    cudaFuncSetAttribute(attn_kernel,
                         cudaFuncAttributeMaxDynamicSharedMemorySize, ATTN_SMEM);

    qkv_kernel<<<dim3(16, 64, 3), 256, GEMM_SMEM>>>(x, Wq, bq, Wk, bk, Wv, bv);
    attn_kernel<<<dim3(32, 64), 256, ATTN_SMEM>>>(mask, att);
    oproj_kernel<<<dim3(16, 64), 256, GEMM_SMEM>>>(Wo, bo, x);
    ln_kernel<<<8192, 256>>>(gamma, beta, out);
}

// round 15
// speedup vs baseline: 1.2335x; 1.1873x over previous
#include <cuda_runtime.h>
#include <cuda_fp16.h>
#include <cstdint>

// Problem constants
constexpr int B_  = 4;
constexpr int S_  = 2048;
constexpr int D_  = 1024;
constexpr int H_  = 16;
constexpr int DK_ = 64;
constexpr float NEGV = -1000000000.0f;

// Scratch (device globals). Q/K/ctx stored fp16; V, pre fp32.
__device__ __align__(16) __half g_Qh[(size_t)B_*H_*S_*DK_];
__device__ __align__(16) __half g_Kh[(size_t)B_*H_*S_*DK_];
__device__ __align__(16) float  g_V [(size_t)B_*H_*S_*DK_];
__device__ __align__(16) __half g_ctx[(size_t)B_*S_*D_];
__device__ __align__(16) float  g_pre[(size_t)B_*S_*D_];

// ---------------------------------------------------------------------------
// helpers
// ---------------------------------------------------------------------------
// pack two fp32 -> half2 (lo goes to low 16 bits). PTX: first source -> upper.
__device__ __forceinline__ uint32_t h2(float lo, float hi) {
    uint32_t r;
    asm("cvt.rn.f16x2.f32 %0, %1, %2;" : "=r"(r) : "f"(hi), "f"(lo));
    return r;
}

__device__ __forceinline__ void mma16(float& c0, float& c1, float& c2, float& c3,
                                      uint32_t a0, uint32_t a1, uint32_t a2, uint32_t a3,
                                      uint32_t b0, uint32_t b1) {
    asm volatile(
        "mma.sync.aligned.m16n8k16.row.col.f32.f16.f16.f32 "
        "{%0,%1,%2,%3},{%4,%5,%6,%7},{%8,%9},{%0,%1,%2,%3};\n"
        : "+f"(c0), "+f"(c1), "+f"(c2), "+f"(c3)
        : "r"(a0), "r"(a1), "r"(a2), "r"(a3), "r"(b0), "r"(b1));
}

__device__ __forceinline__ void cpa16(void* dst, const void* src) {
    uint32_t d = (uint32_t)__cvta_generic_to_shared(dst);
    asm volatile("cp.async.cg.shared.global [%0], [%1], 16;" :: "r"(d), "l"(src));
}
__device__ __forceinline__ void cp_commit() {
    asm volatile("cp.async.commit_group;" ::: "memory");
}
__device__ __forceinline__ void cp_wait1() {
    asm volatile("cp.async.wait_group 1;" ::: "memory");
}
__device__ __forceinline__ void cp_wait0() {
    asm volatile("cp.async.wait_group 0;" ::: "memory");
}

// ---------------------------------------------------------------------------
// Kernel 1: fused QKV projection, fp16 mma, cp.async fp32 staging.
// grid (16 n-tiles=heads, 64 m-tiles, 3), block 256. CTA 128M x 64N, k=32.
// A stride 40 (LDS.64 conflict-free), B stride 76 (24t+g conflict-free).
// Q/K written fp16 (Q scaled 1/8); V written fp32.
// Dynamic smem: A[2][128*40] + B[2][32*76] floats = 60,416 B.
// ---------------------------------------------------------------------------
__global__ __launch_bounds__(256) void qkv_kernel(
    const float* __restrict__ x,
    const float* __restrict__ Wq, const float* __restrict__ bq,
    const float* __restrict__ Wk, const float* __restrict__ bk,
    const float* __restrict__ Wv, const float* __restrict__ bv)
{
    const int z = blockIdx.z;
    const float* W    = (z == 0) ? Wq : ((z == 1) ? Wk : Wv);
    const float* bias = (z == 0) ? bq : ((z == 1) ? bk : bv);
    __half* outh      = (z == 0) ? g_Qh : g_Kh;   // used when z < 2

    const int m0 = blockIdx.y * 128;
    const int n0 = blockIdx.x * 64;
    const int h  = blockIdx.x;

    extern __shared__ float smq[];
    float* As = smq;                  // [2][128*40]
    float* Bs = smq + 2 * 128 * 40;   // [2][32*76]

    const int tid  = threadIdx.x;
    const int wid  = tid >> 5;
    const int lane = tid & 31;
    const int wm   = wid & 3;
    const int wn   = wid >> 2;
    const int g    = lane >> 2;
    const int t    = lane & 3;

    float c[2][4][4];
    #pragma unroll
    for (int i = 0; i < 2; i++)
        #pragma unroll
        for (int j = 0; j < 4; j++)
            #pragma unroll
            for (int r = 0; r < 4; r++) c[i][j][r] = 0.0f;

    auto stage = [&](int k0, int s) {
        float* Ad = As + s * (128 * 40);
        float* Bd = Bs + s * (32 * 76);
        #pragma unroll
        for (int it = 0; it < 4; it++) {
            int idx = tid + it * 256;
            int row = idx >> 3;
            int kc  = (idx & 7) << 2;
            cpa16(Ad + row * 40 + kc, x + (size_t)(m0 + row) * D_ + k0 + kc);
        }
        #pragma unroll
        for (int it = 0; it < 2; it++) {
            int idx = tid + it * 256;
            int k   = idx >> 4;
            int nc  = (idx & 15) << 2;
            cpa16(Bd + k * 76 + nc, W + (size_t)(k0 + k) * D_ + n0 + nc);
        }
        cp_commit();
    };

    stage(0, 0);
    for (int itk = 0; itk < 32; itk++) {
        const int s = itk & 1;
        if (itk < 31) { stage((itk + 1) * 32, s ^ 1); cp_wait1(); }
        else          { cp_wait0(); }
        __syncthreads();

        const float* Ab = As + s * (128 * 40);
        const float* Bb = Bs + s * (32 * 76);
        #pragma unroll
        for (int ks = 0; ks < 2; ks++) {
            const int kk = ks << 4;
            uint32_t a[2][4];
            #pragma unroll
            for (int mi = 0; mi < 2; mi++) {
                int mr = wm * 32 + mi * 16 + g;
                float2 p0 = *(const float2*)&Ab[ mr      * 40 + kk + 2 * t];
                float2 p1 = *(const float2*)&Ab[(mr + 8) * 40 + kk + 2 * t];
                float2 p2 = *(const float2*)&Ab[ mr      * 40 + kk + 8 + 2 * t];
                float2 p3 = *(const float2*)&Ab[(mr + 8) * 40 + kk + 8 + 2 * t];
                a[mi][0] = h2(p0.x, p0.y);
                a[mi][1] = h2(p1.x, p1.y);
                a[mi][2] = h2(p2.x, p2.y);
                a[mi][3] = h2(p3.x, p3.y);
            }
            uint32_t b[4][2];
            #pragma unroll
            for (int ni = 0; ni < 4; ni++) {
                int nc = wn * 32 + ni * 8 + g;
                b[ni][0] = h2(Bb[(kk + 2 * t    ) * 76 + nc],
                              Bb[(kk + 2 * t + 1) * 76 + nc]);
                b[ni][1] = h2(Bb[(kk + 8 + 2 * t    ) * 76 + nc],
                              Bb[(kk + 8 + 2 * t + 1) * 76 + nc]);
            }
            #pragma unroll
            for (int mi = 0; mi < 2; mi++)
                #pragma unroll
                for (int ni = 0; ni < 4; ni++)
                    mma16(c[mi][ni][0], c[mi][ni][1], c[mi][ni][2], c[mi][ni][3],
                          a[mi][0], a[mi][1], a[mi][2], a[mi][3],
                          b[ni][0], b[ni][1]);
        }
        __syncthreads();
    }

    const float scl = (z == 0) ? 0.125f : 1.0f;
    #pragma unroll
    for (int mi = 0; mi < 2; mi++) {
        #pragma unroll
        for (int ni = 0; ni < 4; ni++) {
            int n  = wn * 32 + ni * 8 + 2 * t;
            float b0 = bias[n0 + n], b1 = bias[n0 + n + 1];
            #pragma unroll
            for (int hh = 0; hh < 2; hh++) {
                int m  = m0 + wm * 32 + mi * 16 + g + hh * 8;
                int bb = m >> 11;
                int s2 = m & (S_ - 1);
                size_t base = ((size_t)(bb * H_ + h) * S_ + s2) * DK_ + n;
                float v0 = (c[mi][ni][2 * hh + 0] + b0) * scl;
                float v1 = (c[mi][ni][2 * hh + 1] + b1) * scl;
                if (z < 2) {
                    *(uint32_t*)(outh + base) = h2(v0, v1);
                } else {
                    *(float2*)(g_V + base) = make_float2(v0, v1);
                }
            }
        }
    }
}

// ---------------------------------------------------------------------------
// Kernel 2 (FUSED attention, fp16 mma, single-QK): q-tile 64, 256 threads,
// warp grid 2(q) x 4(k).
//   pass 1: S = Q@K^T (fp16 frags, Q hoisted to regs), e = exp(masked s)
//           -> store e (fp32) to att, accumulate l.
//   pass 2: cp.async e back, p = e/l, rewrite att (fp32), pack half2 p into
//           Ps, ctx += p@V (V staged fp32, packed at frag time). ctx fp16.
// Dynamic smem (uint32 words): Q2/Ps[64*36] | Ec[2][64*68] (pass1: K2[2][64*36]
// in same region) | Vc[2][64*76] = 82,944 B.
// ---------------------------------------------------------------------------
__global__ __launch_bounds__(256, 2) void attn_kernel(
    const int* __restrict__ mask, float* __restrict__ att)
{
    extern __shared__ uint32_t dsm[];
    uint32_t* Q2   = dsm;                    // [64*36] half2 words; Ps in pass 2
    uint32_t* K2B  = dsm + 2304;             // pass1 [2][64*36]
    uint32_t* EsB[2] = { dsm + 2304, dsm + 2304 + 4352 };  // pass2 fp32 [64*68]
    uint32_t* VcB  = dsm + 2304 + 8704;      // [2][64*76] fp32

    __shared__ float red_l[64][4];
    __shared__ float sl[64];

    const int bh = blockIdx.y;
    const int q0 = blockIdx.x * 64;
    const int bb = bh >> 4;

    const __half* Qb = g_Qh + (size_t)bh * S_ * DK_;
    const __half* Kb = g_Kh + (size_t)bh * S_ * DK_;
    const float*  Vb = g_V  + (size_t)bh * S_ * DK_;

    const int tid  = threadIdx.x;
    const int wid  = tid >> 5;
    const int lane = tid & 31;
    const int wq   = wid & 1;
    const int wk   = wid >> 1;
    const int g    = lane >> 2;
    const int t    = lane & 3;

    // stage Q tile (64 x 64 halves = 64 x 32 words), stride 36
    #pragma unroll
    for (int it = 0; it < 2; it++) {
        int idx = tid + it * 256;
        int row = idx >> 3;
        int cw  = (idx & 7) << 2;
        cpa16(Q2 + row * 36 + cw, Qb + (size_t)(q0 + row) * DK_ + cw * 2);
    }
    cp_commit(); cp_wait0();
    __syncthreads();

    // hoist Q a-fragments (k16 steps: 4)
    uint32_t qf[2][4][4];
    #pragma unroll
    for (int mi = 0; mi < 2; mi++) {
        int qr = wq * 32 + mi * 16 + g;
        #pragma unroll
        for (int ks = 0; ks < 4; ks++) {
            qf[mi][ks][0] = Q2[ qr      * 36 + 8 * ks + t];
            qf[mi][ks][1] = Q2[(qr + 8) * 36 + 8 * ks + t];
            qf[mi][ks][2] = Q2[ qr      * 36 + 8 * ks + 4 + t];
            qf[mi][ks][3] = Q2[(qr + 8) * 36 + 8 * ks + 4 + t];
        }
    }
    __syncthreads();   // Q2 dead; K2B overlays nothing yet

    const int* mrow = mask + bb * S_;
    float* attQ = att + (size_t)bh * S_ * S_ + (size_t)q0 * S_;

    auto stageK = [&](int kt, int s) {
        uint32_t* Kd = K2B + s * 2304;
        const __half* src = Kb + (size_t)(kt * 64) * DK_;
        #pragma unroll
        for (int it = 0; it < 2; it++) {
            int idx = tid + it * 256;
            int row = idx >> 3;
            int cw  = (idx & 7) << 2;
            cpa16(Kd + row * 36 + cw, src + (size_t)row * DK_ + cw * 2);
        }
    };
    auto stageV = [&](int kt, int s) {
        uint32_t* Vd = VcB + s * (64 * 76);
        const float* src = Vb + (size_t)(kt * 64) * DK_;
        #pragma unroll
        for (int it = 0; it < 4; it++) {
            int idx = tid + it * 256;
            int row = idx >> 4;
            int dc  = (idx & 15) << 2;
            cpa16(Vd + row * 76 + dc, src + (size_t)row * DK_ + dc);
        }
    };
    auto stageE = [&](int kt, int s) {
        uint32_t* Ed = EsB[s];
        const float* src = attQ + kt * 64;
        #pragma unroll
        for (int it = 0; it < 4; it++) {
            int idx = tid + it * 256;
            int row = idx >> 4;
            int kc  = (idx & 15) << 2;
            cpa16(Ed + row * 68 + kc, src + (size_t)row * S_ + kc);
        }
    };

    // ---------------- pass 1: e = exp(s) -> att, l = sum e ----------------
    float rl[4] = {0.0f, 0.0f, 0.0f, 0.0f};

    stageK(0, 0); cp_commit();
    for (int kt = 0; kt < 32; kt++) {
        const int s = kt & 1;
        if (kt < 31) { stageK(kt + 1, s ^ 1); cp_commit(); cp_wait1(); }
        else         { cp_wait0(); }
        __syncthreads();

        const uint32_t* Kc = K2B + s * 2304;
        float c[2][2][4];
        #pragma unroll
        for (int mi = 0; mi < 2; mi++)
            #pragma unroll
            for (int ni = 0; ni < 2; ni++)
                #pragma unroll
                for (int r = 0; r < 4; r++) c[mi][ni][r] = 0.0f;

        #pragma unroll
        for (int ks = 0; ks < 4; ks++) {
            uint32_t b[2][2];
            #pragma unroll
            for (int ni = 0; ni < 2; ni++) {
                int kc = wk * 16 + ni * 8 + g;
                b[ni][0] = Kc[kc * 36 + 8 * ks + t];
                b[ni][1] = Kc[kc * 36 + 8 * ks + 4 + t];
            }
            #pragma unroll
            for (int mi = 0; mi < 2; mi++)
                #pragma unroll
                for (int ni = 0; ni < 2; ni++)
                    mma16(c[mi][ni][0], c[mi][ni][1], c[mi][ni][2], c[mi][ni][3],
                          qf[mi][ks][0], qf[mi][ks][1], qf[mi][ks][2], qf[mi][ks][3],
                          b[ni][0], b[ni][1]);
        }

        #pragma unroll
        for (int ni = 0; ni < 2; ni++) {
            int kg = kt * 64 + wk * 16 + ni * 8 + 2 * t;
            bool mz0 = (mrow[kg] == 0);
            bool mz1 = (mrow[kg + 1] == 0);
            #pragma unroll
            for (int mi = 0; mi < 2; mi++) {
                #pragma unroll
                for (int hh = 0; hh < 2; hh++) {
                    int q = wq * 32 + mi * 16 + g + hh * 8;
                    float v0 = mz0 ? NEGV : c[mi][ni][2 * hh + 0];
                    float v1 = mz1 ? NEGV : c[mi][ni][2 * hh + 1];
                    float e0 = __expf(v0);
                    float e1 = __expf(v1);
                    rl[mi * 2 + hh] += e0 + e1;
                    *(float2*)(attQ + (size_t)q * S_ + kg) = make_float2(e0, e1);
                }
            }
        }
        __syncthreads();
    }

    #pragma unroll
    for (int i = 0; i < 4; i++) {
        rl[i] += __shfl_xor_sync(0xffffffffu, rl[i], 1);
        rl[i] += __shfl_xor_sync(0xffffffffu, rl[i], 2);
    }
    if (t == 0) {
        #pragma unroll
        for (int mi = 0; mi < 2; mi++)
            #pragma unroll
            for (int hh = 0; hh < 2; hh++) {
                int q = wq * 32 + mi * 16 + g + hh * 8;
                red_l[q][wk] = rl[mi * 2 + hh];
            }
    }
    __syncthreads();
    if (tid < 64) {
        sl[tid] = 1.0f / (red_l[tid][0] + red_l[tid][1] + red_l[tid][2] + red_l[tid][3]);
    }
    __syncthreads();

    // ---------------- pass 2: reload e, p = e/l, rewrite att, AV ----------------
    uint32_t* Ps = Q2;   // fragment-ready half2 p tile, stride 36
    float co[2][2][4];
    #pragma unroll
    for (int mi = 0; mi < 2; mi++)
        #pragma unroll
        for (int ni = 0; ni < 2; ni++)
            #pragma unroll
            for (int r = 0; r < 4; r++) co[mi][ni][r] = 0.0f;

    stageE(0, 0); stageV(0, 0); cp_commit();
    for (int kt = 0; kt < 32; kt++) {
        const int s = kt & 1;
        if (kt < 31) { stageE(kt + 1, s ^ 1); stageV(kt + 1, s ^ 1); cp_commit(); cp_wait1(); }
        else         { cp_wait0(); }
        __syncthreads();

        uint32_t* Ec = EsB[s];
        const float* Vc = (const float*)(VcB + s * (64 * 76));

        // normalize sweep: p = e/l -> att (fp32) + Ps (half2, stride 36)
        #pragma unroll
        for (int it = 0; it < 4; it++) {
            int idx = tid + it * 256;
            int row = idx >> 4;
            int kc  = (idx & 15) << 2;
            float4 e = *(float4*)&Ec[row * 68 + kc];
            float il = sl[row];
            float4 p;
            p.x = e.x * il; p.y = e.y * il; p.z = e.z * il; p.w = e.w * il;
            *(float4*)(attQ + (size_t)row * S_ + kt * 64 + kc) = p;
            uint2 ph = make_uint2(h2(p.x, p.y), h2(p.z, p.w));
            *(uint2*)&Ps[row * 36 + (kc >> 1)] = ph;
        }
        __syncthreads();

        // AV mma: co += P @ V
        #pragma unroll
        for (int ks = 0; ks < 4; ks++) {
            const int kk = ks << 4;
            uint32_t a[2][4];
            #pragma unroll
            for (int mi = 0; mi < 2; mi++) {
                int qr = wq * 32 + mi * 16 + g;
                a[mi][0] = Ps[ qr      * 36 + 8 * ks + t];
                a[mi][1] = Ps[(qr + 8) * 36 + 8 * ks + t];
                a[mi][2] = Ps[ qr      * 36 + 8 * ks + 4 + t];
                a[mi][3] = Ps[(qr + 8) * 36 + 8 * ks + 4 + t];
            }
            uint32_t b[2][2];
            #pragma unroll
            for (int ni = 0; ni < 2; ni++) {
                int dc = wk * 16 + ni * 8 + g;
                b[ni][0] = h2(Vc[(kk + 2 * t    ) * 76 + dc],
                              Vc[(kk + 2 * t + 1) * 76 + dc]);
                b[ni][1] = h2(Vc[(kk + 8 + 2 * t    ) * 76 + dc],
                              Vc[(kk + 8 + 2 * t + 1) * 76 + dc]);
            }
            #pragma unroll
            for (int mi = 0; mi < 2; mi++)
                #pragma unroll
                for (int ni = 0; ni < 2; ni++)
                    mma16(co[mi][ni][0], co[mi][ni][1], co[mi][ni][2], co[mi][ni][3],
                          a[mi][0], a[mi][1], a[mi][2], a[mi][3],
                          b[ni][0], b[ni][1]);
        }
        __syncthreads();
    }

    const int h = bh & 15;
    #pragma unroll
    for (int mi = 0; mi < 2; mi++) {
        #pragma unroll
        for (int ni = 0; ni < 2; ni++) {
            int d = wk * 16 + ni * 8 + 2 * t;
            #pragma unroll
            for (int hh = 0; hh < 2; hh++) {
                int q = q0 + wq * 32 + mi * 16 + g + hh * 8;
                uint32_t o = h2(co[mi][ni][2 * hh + 0], co[mi][ni][2 * hh + 1]);
                *(uint32_t*)(g_ctx + ((size_t)(bb * S_ + q)) * D_ + h * DK_ + d) = o;
            }
        }
    }
}

// ---------------------------------------------------------------------------
// Kernel 4: out_pre = ctx @ Wo + bo + x  (fp16 mma, cp.async, residual fused).
// ctx fp16 (no cvt on A); Wo fp32 packed at frag time. CTA 128x64, k=64.
// Dynamic smem: A2[2][128*36] words + B[2][64*76] floats = 75,776 B.
// ---------------------------------------------------------------------------
__global__ __launch_bounds__(256) void oproj_kernel(
    const float* __restrict__ Wo, const float* __restrict__ bo,
    const float* __restrict__ x)
{
    const int m0 = blockIdx.y * 128;
    const int n0 = blockIdx.x * 64;

    extern __shared__ uint32_t smo[];
    uint32_t* A2 = smo;                   // [2][128*36] half2 words
    float*    Bs = (float*)(smo + 2 * 128 * 36);   // [2][64*76]

    const int tid  = threadIdx.x;
    const int wid  = tid >> 5;
    const int lane = tid & 31;
    const int wm   = wid & 3;
    const int wn   = wid >> 2;
    const int g    = lane >> 2;
    const int t    = lane & 3;

    float c[2][4][4];
    #pragma unroll
    for (int i = 0; i < 2; i++)
        #pragma unroll
        for (int j = 0; j < 4; j++)
            #pragma unroll
            for (int r = 0; r < 4; r++) c[i][j][r] = 0.0f;

    auto stage = [&](int k0, int s) {       // k0 in halves/floats (D units)
        uint32_t* Ad = A2 + s * (128 * 36);
        float*    Bd = Bs + s * (64 * 76);
        #pragma unroll
        for (int it = 0; it < 4; it++) {
            int idx = tid + it * 256;
            int row = idx >> 3;
            int cw  = (idx & 7) << 2;       // word offset within 32-word row
            cpa16(Ad + row * 36 + cw,
                  g_ctx + (size_t)(m0 + row) * D_ + k0 + cw * 2);
        }
        #pragma unroll
        for (int it = 0; it < 4; it++) {
            int idx = tid + it * 256;
            int kr  = idx >> 4;
            int fc  = (idx & 15) << 2;
            cpa16(Bd + kr * 76 + fc, Wo + (size_t)(k0 + kr) * D_ + n0 + fc);
        }
        cp_commit();
    };

    stage(0, 0);
    for (int itk = 0; itk < 16; itk++) {
        const int s = itk & 1;
        if (itk < 15) { stage((itk + 1) * 64, s ^ 1); cp_wait1(); }
        else          { cp_wait0(); }
        __syncthreads();

        const uint32_t* Ab = A2 + s * (128 * 36);
        const float*    Bb = Bs + s * (64 * 76);
        #pragma unroll
        for (int ks = 0; ks < 4; ks++) {
            const int kk = ks << 4;         // fp32/half index base
            uint32_t a[2][4];
            #pragma unroll
            for (int mi = 0; mi < 2; mi++) {
                int mr = wm * 32 + mi * 16 + g;
                a[mi][0] = Ab[ mr      * 36 + 8 * ks + t];
                a[mi][1] = Ab[(mr + 8) * 36 + 8 * ks + t];
                a[mi][2] = Ab[ mr      * 36 + 8 * ks + 4 + t];
                a[mi][3] = Ab[(mr + 8) * 36 + 8 * ks + 4 + t];
            }
            uint32_t b[4][2];
            #pragma unroll
            for (int ni = 0; ni < 4; ni++) {
                int nc = wn * 32 + ni * 8 + g;
                b[ni][0] = h2(Bb[(kk + 2 * t    ) * 76 + nc],
                              Bb[(kk + 2 * t + 1) * 76 + nc]);
                b[ni][1] = h2(Bb[(kk + 8 + 2 * t    ) * 76 + nc],
                              Bb[(kk + 8 + 2 * t + 1) * 76 + nc]);
            }
            #pragma unroll
            for (int mi = 0; mi < 2; mi++)
                #pragma unroll
                for (int ni = 0; ni < 4; ni++)
                    mma16(c[mi][ni][0], c[mi][ni][1], c[mi][ni][2], c[mi][ni][3],
                          a[mi][0], a[mi][1], a[mi][2], a[mi][3],
                          b[ni][0], b[ni][1]);
        }
        __syncthreads();
    }

    #pragma unroll
    for (int mi = 0; mi < 2; mi++) {
        #pragma unroll
        for (int ni = 0; ni < 4; ni++) {
            int n = n0 + wn * 32 + ni * 8 + 2 * t;
            float b0 = bo[n], b1 = bo[n + 1];
            #pragma unroll
            for (int hh = 0; hh < 2; hh++) {
                int m = m0 + wm * 32 + mi * 16 + g + hh * 8;
                float2 xr = *(const float2*)(x + (size_t)m * D_ + n);
                float2 o;
                o.x = c[mi][ni][2 * hh + 0] + b0 + xr.x;
                o.y = c[mi][ni][2 * hh + 1] + b1 + xr.y;
                *(float2*)(g_pre + (size_t)m * D_ + n) = o;
            }
        }
    }
}

// ---------------------------------------------------------------------------
// Kernel 5: rowwise LayerNorm.  grid 8192, block 256.
// ---------------------------------------------------------------------------
__global__ __launch_bounds__(256) void ln_kernel(
    const float* __restrict__ gamma, const float* __restrict__ beta,
    float* __restrict__ out)
{
    const int row = blockIdx.x;
    const float* pr = g_pre + (size_t)row * D_;

    float s = 0.0f, ss = 0.0f;
    for (int i = threadIdx.x; i < D_; i += 256) {
        float t = pr[i];
        s += t; ss += t * t;
    }
    #pragma unroll
    for (int o = 16; o > 0; o >>= 1) {
        s  += __shfl_down_sync(0xffffffffu, s, o);
        ss += __shfl_down_sync(0xffffffffu, ss, o);
    }
    __shared__ float rs[8], rss[8];
    __shared__ float s_mu, s_inv;
    int w = threadIdx.x >> 5, lane = threadIdx.x & 31;
    if (lane == 0) { rs[w] = s; rss[w] = ss; }
    __syncthreads();
    if (threadIdx.x == 0) {
        float S = 0.0f, SS = 0.0f;
        #pragma unroll
        for (int q = 0; q < 8; q++) { S += rs[q]; SS += rss[q]; }
        float mu  = S * (1.0f / (float)D_);
        float var = SS * (1.0f / (float)D_) - mu * mu;
        var = fmaxf(var, 0.0f);
        s_mu  = mu;
        s_inv = rsqrtf(var + 1e-5f);
    }
    __syncthreads();
    float mu = s_mu, inv = s_inv;
    for (int i = threadIdx.x; i < D_; i += 256) {
        out[(size_t)row * D_ + i] = (pr[i] - mu) * inv * gamma[i] + beta[i];
    }
}

// ---------------------------------------------------------------------------
extern "C" void kernel_launch(void* const* d_in, const int* in_sizes, int n_in,
                              void* d_out, int out_size)
{
    const float* x     = (const float*)d_in[0];
    const int*   mask  = (const int*)  d_in[1];
    const float* Wq    = (const float*)d_in[2];
    const float* bq    = (const float*)d_in[3];
    const float* Wk    = (const float*)d_in[4];
    const float* bk    = (const float*)d_in[5];
    const float* Wv    = (const float*)d_in[6];
    const float* bv    = (const float*)d_in[7];
    const float* Wo    = (const float*)d_in[8];
    const float* bo    = (const float*)d_in[9];
    const float* gamma = (const float*)d_in[10];
    const float* beta  = (const float*)d_in[11];

    float* out = (float*)d_out;
    float* att = out + (size_t)B_ * S_ * D_;

    constexpr int QKV_SMEM   = (2 * 128 * 40 + 2 * 32 * 76) * 4;          // 60,416 B
    constexpr int ATTN_SMEM  = (2304 + 2 * 64 * 68 + 2 * 64 * 76) * 4;    // 82,944 B
    constexpr int OPROJ_SMEM = (2 * 128 * 36 + 2 * 64 * 76) * 4;          // 75,776 B

    cudaFuncSetAttribute(qkv_kernel,
                         cudaFuncAttributeMaxDynamicSharedMemorySize, QKV_SMEM);
    cudaFuncSetAttribute(attn_kernel,
                         cudaFuncAttributeMaxDynamicSharedMemorySize, ATTN_SMEM);
    cudaFuncSetAttribute(oproj_kernel,
                         cudaFuncAttributeMaxDynamicSharedMemorySize, OPROJ_SMEM);

    qkv_kernel<<<dim3(16, 64, 3), 256, QKV_SMEM>>>(x, Wq, bq, Wk, bk, Wv, bv);
    attn_kernel<<<dim3(32, 64), 256, ATTN_SMEM>>>(mask, att);
    oproj_kernel<<<dim3(16, 64), 256, OPROJ_SMEM>>>(Wo, bo, x);
    ln_kernel<<<8192, 256>>>(gamma, beta, out);
}